// round 12
// baseline (speedup 1.0000x reference)
#include <cuda_runtime.h>
#include <cuda_bf16.h>

typedef unsigned long long ull;
typedef unsigned int u32;

#define NV      100000
#define NE      1600000
#define GRIDW   128
#define G3      (GRIDW*GRIDW*GRIDW)
#define BCAP    128          // neighbor bucket capacity per vertex

// ---------------- device scratch ----------------
__device__ int   g_cursor[NV];     // zero-initialized; k_fin2 re-zeroes each launch
__device__ int   g_csr[NV * BCAP];

__device__ __align__(16) __nv_bfloat16 g_IT[G3 * 16];    // channels-last image (bf16)
__device__ __align__(16) __nv_bfloat16 g_X0[NV * 32];
__device__ __align__(16) __nv_bfloat16 g_X1[NV * 32];
__device__ __align__(16) __nv_bfloat16 g_X2[NV * 64];
__device__ float4 g_P[NV];    // h3 @ Wn3
__device__ float4 g_S[NV];    // h3 @ Ws3 + b3

// ---------------- helpers ----------------
__device__ __forceinline__ ull pack2(float lo, float hi) {
    ull r; asm("mov.b64 %0, {%1,%2};" : "=l"(r) : "f"(lo), "f"(hi)); return r;
}
__device__ __forceinline__ float2 unpack2(ull v) {
    float2 f; asm("mov.b64 {%0,%1}, %2;" : "=f"(f.x), "=f"(f.y) : "l"(v)); return f;
}
__device__ __forceinline__ ull add2(ull a, ull b) {
    ull d; asm("add.rn.f32x2 %0, %1, %2;" : "=l"(d) : "l"(a), "l"(b)); return d;
}
__device__ __forceinline__ ull mul2(ull a, ull b) {
    ull d; asm("mul.rn.f32x2 %0, %1, %2;" : "=l"(d) : "l"(a), "l"(b)); return d;
}
__device__ __forceinline__ ull bf2f2(u32 p) {
    u32 lo = p << 16;
    u32 hi = p & 0xFFFF0000u;
    ull r; asm("mov.b64 %0, {%1,%2};" : "=l"(r) : "r"(lo), "r"(hi)); return r;
}
__device__ __forceinline__ u32 f2bf2(ull v) {
    float2 f = unpack2(v);
    __nv_bfloat162 b = __float22bfloat162_rn(f);
    return *(u32*)&b;
}
__device__ __forceinline__ u32 f2bf2s(float lo, float hi) {
    __nv_bfloat162 b = __float22bfloat162_rn(make_float2(lo, hi));
    return *(u32*)&b;
}
__device__ __forceinline__ u32 smaddr(const void* p) {
    return (u32)__cvta_generic_to_shared(p);
}
__device__ __forceinline__ void ldsm_x4(u32& r0, u32& r1, u32& r2, u32& r3, u32 a) {
    asm volatile("ldmatrix.sync.aligned.m8n8.x4.shared.b16 {%0,%1,%2,%3}, [%4];"
                 : "=r"(r0), "=r"(r1), "=r"(r2), "=r"(r3) : "r"(a));
}
__device__ __forceinline__ void ldsm_x2(u32& r0, u32& r1, u32 a) {
    asm volatile("ldmatrix.sync.aligned.m8n8.x2.shared.b16 {%0,%1}, [%2];"
                 : "=r"(r0), "=r"(r1) : "r"(a));
}
__device__ __forceinline__ void mma_bf16(float& d0, float& d1, float& d2, float& d3,
                                         u32 a0, u32 a1, u32 a2, u32 a3,
                                         u32 b0, u32 b1) {
    asm volatile(
        "mma.sync.aligned.m16n8k16.row.col.f32.bf16.bf16.f32 "
        "{%0,%1,%2,%3}, {%4,%5,%6,%7}, {%8,%9}, {%0,%1,%2,%3};"
        : "+f"(d0), "+f"(d1), "+f"(d2), "+f"(d3)
        : "r"(a0), "r"(a1), "r"(a2), "r"(a3), "r"(b0), "r"(b1));
}

// ---------------- fused: image transpose || edge scatter ----------------
// blocks [0, 16384): transpose [16][x][y][z] f32 -> [x][y][z][16] bf16
// blocks [16384, 19509): bucket scatter (cursors zeroed by previous k_fin2 /
//                         static zero-init on first run)
#define TR_BLOCKS (GRIDW * GRIDW)
#define SC_BLOCKS (NE / 4 / 128)       // 3125

__global__ void __launch_bounds__(128)
k_trsc(const float* __restrict__ img,
       const int4* __restrict__ src4, const int4* __restrict__ dst4)
{
    __shared__ __align__(16) __nv_bfloat16 s[128 * 16];
    int t = threadIdx.x;
    if (blockIdx.x < TR_BLOCKS) {
        int base = blockIdx.x * 128;
#pragma unroll
        for (int c = 0; c < 16; c++) {
            float v = img[(size_t)c * G3 + base + t];
            s[t * 16 + c] = __float2bfloat16(v);
        }
        __syncthreads();
        const uint4* sp = (const uint4*)s;
        uint4* gp = (uint4*)&g_IT[(size_t)base * 16];
        gp[t]       = sp[t];
        gp[t + 128] = sp[t + 128];
    } else {
        int e = (blockIdx.x - TR_BLOCKS) * 128 + t;   // < NE/4 exactly
        int4 sv = src4[e];
        int4 dv = dst4[e];
        int p;
        p = atomicAdd(&g_cursor[dv.x], 1); g_csr[dv.x * BCAP + p] = sv.x;
        p = atomicAdd(&g_cursor[dv.y], 1); g_csr[dv.y * BCAP + p] = sv.y;
        p = atomicAdd(&g_cursor[dv.z], 1); g_csr[dv.z * BCAP + p] = sv.z;
        p = atomicAdd(&g_cursor[dv.w], 1); g_csr[dv.w * BCAP + p] = sv.w;
    }
}

// ---------------- trilinear sampling from channels-last bf16 volume ----------------
__global__ void __launch_bounds__(256)
k_sample(const float* __restrict__ verts)
{
    int v = blockIdx.x * blockDim.x + threadIdx.x;
    if (v >= NV) return;

    float px = verts[v * 3 + 0];
    float py = verts[v * 3 + 1];
    float pz = verts[v * 3 + 2];

    float cx = fminf(fmaxf(px, 0.0f), 127.0f);
    float cy = fminf(fmaxf(py, 0.0f), 127.0f);
    float cz = fminf(fmaxf(pz, 0.0f), 127.0f);
    float fx0 = floorf(cx), fy0 = floorf(cy), fz0 = floorf(cz);
    int x0 = (int)fx0, y0 = (int)fy0, z0 = (int)fz0;
    int x1 = min(x0 + 1, 127), y1 = min(y0 + 1, 127), z1 = min(z0 + 1, 127);
    float wx = cx - fx0, wy = cy - fy0, wz = cz - fz0;

    float f[16];
#pragma unroll
    for (int c = 0; c < 16; c++) f[c] = 0.0f;

    int xs[2] = {x0, x1}; int ys[2] = {y0, y1}; int zs[2] = {z0, z1};
    float wxa[2] = {1.0f - wx, wx};
    float wya[2] = {1.0f - wy, wy};
    float wza[2] = {1.0f - wz, wz};

#pragma unroll
    for (int a = 0; a < 2; a++)
#pragma unroll
    for (int b = 0; b < 2; b++)
#pragma unroll
    for (int cc = 0; cc < 2; cc++) {
        float w = wxa[a] * wya[b] * wza[cc];
        size_t idx = ((size_t)((xs[a] << 14) + (ys[b] << 7) + zs[cc])) << 4;
        uint4 p0 = *(const uint4*)&g_IT[idx];
        uint4 p1 = *(const uint4*)&g_IT[idx + 8];
        const u32 pk[8] = {p0.x, p0.y, p0.z, p0.w, p1.x, p1.y, p1.z, p1.w};
#pragma unroll
        for (int j = 0; j < 8; j++) {
            float2 two = unpack2(bf2f2(pk[j]));
            f[2 * j]     += w * two.x;
            f[2 * j + 1] += w * two.y;
        }
    }

    float e[32];
    e[0] = px * (1.0f / 128.0f);
    e[1] = py * (1.0f / 128.0f);
    e[2] = pz * (1.0f / 128.0f);
#pragma unroll
    for (int c = 0; c < 16; c++) e[3 + c] = f[c];
#pragma unroll
    for (int c = 19; c < 32; c++) e[c] = 0.0f;

    u32 w8[16];
#pragma unroll
    for (int j = 0; j < 16; j++) w8[j] = f2bf2s(e[2 * j], e[2 * j + 1]);
    uint4* dst = (uint4*)&g_X0[(size_t)v * 32];
    dst[0] = make_uint4(w8[0], w8[1], w8[2], w8[3]);
    dst[1] = make_uint4(w8[4], w8[5], w8[6], w8[7]);
    dst[2] = make_uint4(w8[8], w8[9], w8[10], w8[11]);
    dst[3] = make_uint4(w8[12], w8[13], w8[14], w8[15]);
}

// ---------------- fused gather + tensor-core layer GEMM ----------------
// Per block of M vertices: stage [X | mean-gather] into As smem, then
// Y = leaky(As @ Wt^T + b). If PROJ: compute S/P final projections instead.
template<int M, int K, int DOUT, bool RELU, bool PROJ>
__global__ void __launch_bounds__(256)
k_layer(const __nv_bfloat16* __restrict__ X, __nv_bfloat16* __restrict__ Y,
        const float* __restrict__ Wsg, const float* __restrict__ Wng,
        const float* __restrict__ Bg, int din_real,
        const float* __restrict__ Ws3, const float* __restrict__ Wn3,
        const float* __restrict__ B3)
{
    constexpr int RS  = K + 8;
    constexpr int DIN = K / 2;
    constexpr int CH  = DIN / 8;        // uint4 per row half
    constexpr int NT  = DOUT / 16;
    constexpr int MH  = M / 64;
    constexpr int MW  = M / 8;          // vertices per warp (gather phase)
    constexpr int GSZ = DIN / 4;        // lanes per row (uint2 each)
    constexpr int PAR = 32 / GSZ;       // neighbors per step

    __shared__ __align__(16) __nv_bfloat16 As[M * RS];
    __shared__ __align__(16) __nv_bfloat16 Wt[DOUT * RS];
    __shared__ float Bs[DOUT];

    int tid = threadIdx.x;
    int warp = tid >> 5, lane = tid & 31;
    int vbase = blockIdx.x * M;

    // ---- stage transposed concat weights ----
    for (int idx = tid; idx < DOUT * K; idx += 256) {
        int n = idx / K, k = idx % K;
        int kh = (k < DIN) ? k : k - DIN;
        float val = 0.0f;
        if (kh < din_real) val = ((k < DIN) ? Wsg : Wng)[kh * DOUT + n];
        Wt[n * RS + k] = __float2bfloat16(val);
    }
    if (tid < DOUT) Bs[tid] = Bg[tid];

    // ---- stage X rows (left half of As) ----
    for (int idx = tid; idx < M * CH; idx += 256) {
        int r = idx / CH, c8 = idx % CH;
        int v = min(vbase + r, NV - 1);
        *(uint4*)&As[r * RS + c8 * 8] = *(const uint4*)&X[(size_t)v * DIN + c8 * 8];
    }

    // ---- gather phase: warp handles MW vertices, result -> right half of As ----
    {
        int w0 = warp * MW;
        int dvec = 0;
        if (lane < MW) {
            int vv = vbase + w0 + lane;
            dvec = (vv < NV) ? g_cursor[vv] : 0;
        }
        int sub  = lane / GSZ;
        int cole = (lane & (GSZ - 1)) * 4;

        int idxc = g_csr[(size_t)min(vbase + w0, NV - 1) * BCAP + lane];
        for (int m = 0; m < MW; m++) {
            int d = __shfl_sync(0xFFFFFFFFu, dvec, m);
            int vnx = min(vbase + w0 + m + 1, NV - 1);
            int idxn = g_csr[(size_t)vnx * BCAP + lane];   // prefetch next vertex

            ull a0 = 0ull, a1 = 0ull;
            int kl = min(d, 32);
            for (int k = 0; k < kl; k += PAR) {
                int s = __shfl_sync(0xFFFFFFFFu, idxc, k + sub);
                uint2 p = make_uint2(0u, 0u);
                if (k + sub < d) p = *(const uint2*)&X[(size_t)s * DIN + cole];
                a0 = add2(a0, bf2f2(p.x));
                a1 = add2(a1, bf2f2(p.y));
            }
            if (d > 32) {                       // rare (P ~1e-4)
                size_t oc = (size_t)min(vbase + w0 + m, NV - 1) * BCAP;
                for (int k = 32 + sub; k < d; k += PAR) {
                    int s = g_csr[oc + k];
                    uint2 p = *(const uint2*)&X[(size_t)s * DIN + cole];
                    a0 = add2(a0, bf2f2(p.x));
                    a1 = add2(a1, bf2f2(p.y));
                }
            }
#pragma unroll
            for (int msk = GSZ; msk < 32; msk <<= 1) {
                a0 = add2(a0, __shfl_xor_sync(0xFFFFFFFFu, a0, msk));
                a1 = add2(a1, __shfl_xor_sync(0xFFFFFFFFu, a1, msk));
            }
            float inv = 1.0f / fmaxf((float)d, 1.0f);
            ull inv2 = pack2(inv, inv);
            if (sub == 0) {
                uint2 ov;
                ov.x = f2bf2(mul2(a0, inv2));
                ov.y = f2bf2(mul2(a1, inv2));
                *(uint2*)&As[(w0 + m) * RS + DIN + cole] = ov;
            }
            idxc = idxn;
        }
    }
    __syncthreads();

    // ---- MMA phase ----
    int wm = warp & 3;
    int wn = warp >> 2;
    int nb = wn * (DOUT / 2);

    float d[MH][NT][4];
#pragma unroll
    for (int nt = 0; nt < NT; nt++) {
        float c0 = Bs[nb + nt * 8 + (lane & 3) * 2];
        float c1 = Bs[nb + nt * 8 + (lane & 3) * 2 + 1];
#pragma unroll
        for (int mh = 0; mh < MH; mh++) {
            d[mh][nt][0] = c0; d[mh][nt][1] = c1;
            d[mh][nt][2] = c0; d[mh][nt][3] = c1;
        }
    }

#pragma unroll
    for (int ks = 0; ks < K / 16; ks++) {
        int k0 = ks * 16;
        u32 a[MH][4];
#pragma unroll
        for (int mh = 0; mh < MH; mh++) {
            int m0 = mh * 64 + wm * 16;
            u32 aaddr = smaddr(&As[(m0 + (lane & 15)) * RS + k0 + (lane >> 4) * 8]);
            ldsm_x4(a[mh][0], a[mh][1], a[mh][2], a[mh][3], aaddr);
        }
#pragma unroll
        for (int nt = 0; nt < NT; nt++) {
            u32 b0, b1;
            u32 baddr = smaddr(&Wt[(nb + nt * 8 + (lane & 7)) * RS + k0 + ((lane >> 3) & 1) * 8]);
            ldsm_x2(b0, b1, baddr);
#pragma unroll
            for (int mh = 0; mh < MH; mh++)
                mma_bf16(d[mh][nt][0], d[mh][nt][1], d[mh][nt][2], d[mh][nt][3],
                         a[mh][0], a[mh][1], a[mh][2], a[mh][3], b0, b1);
        }
    }

    if (PROJ) __syncthreads();   // all ldmatrix reads of As done before overwrite

#pragma unroll
    for (int mh = 0; mh < MH; mh++) {
        int rb = mh * 64 + wm * 16 + (lane >> 2);
#pragma unroll
        for (int nt = 0; nt < NT; nt++) {
            int col = nb + nt * 8 + (lane & 3) * 2;
            float y0 = d[mh][nt][0], y1 = d[mh][nt][1], y2 = d[mh][nt][2], y3 = d[mh][nt][3];
            if (RELU) {
                y0 = fmaxf(y0, 0.3f * y0); y1 = fmaxf(y1, 0.3f * y1);
                y2 = fmaxf(y2, 0.3f * y2); y3 = fmaxf(y3, 0.3f * y3);
            }
            if (PROJ) {
                float* r0 = (float*)&As[(size_t)rb * RS];
                float* r1 = (float*)&As[(size_t)(rb + 8) * RS];
                r0[col] = y0; r0[col + 1] = y1;
                r1[col] = y2; r1[col + 1] = y3;
            } else {
                int row0 = vbase + rb;
                if (row0 < NV)
                    *(u32*)&Y[(size_t)row0 * DOUT + col] = f2bf2s(y0, y1);
                if (row0 + 8 < NV)
                    *(u32*)&Y[(size_t)(row0 + 8) * DOUT + col] = f2bf2s(y2, y3);
            }
        }
    }

    if (PROJ) {
        __syncthreads();
        float ws[2][3], wnv[2][3];
#pragma unroll
        for (int e2 = 0; e2 < 2; e2++)
#pragma unroll
            for (int c = 0; c < 3; c++) {
                ws[e2][c]  = Ws3[(2 * lane + e2) * 3 + c];
                wnv[e2][c] = Wn3[(2 * lane + e2) * 3 + c];
            }
        float b0 = B3[0], b1 = B3[1], b2 = B3[2];

        for (int i = 0; i < M / 8; i++) {
            int r = warp * (M / 8) + i;
            int v = vbase + r;
            if (v >= NV) break;
            const float* hrow = (const float*)&As[(size_t)r * RS];
            float2 h2 = *(const float2*)&hrow[2 * lane];
            float as[3], an[3];
#pragma unroll
            for (int c = 0; c < 3; c++) {
                as[c] = h2.x * ws[0][c] + h2.y * ws[1][c];
                an[c] = h2.x * wnv[0][c] + h2.y * wnv[1][c];
            }
#pragma unroll
            for (int off = 16; off > 0; off >>= 1) {
#pragma unroll
                for (int c = 0; c < 3; c++) {
                    as[c] += __shfl_xor_sync(0xFFFFFFFFu, as[c], off);
                    an[c] += __shfl_xor_sync(0xFFFFFFFFu, an[c], off);
                }
            }
            if (lane == 0) {
                g_S[v] = make_float4(as[0] + b0, as[1] + b1, as[2] + b2, 0.0f);
                g_P[v] = make_float4(an[0], an[1], an[2], 0.0f);
            }
        }
    }
}

// ---------------- final: 3-wide gather + output (+ cursor re-zero) ----------------
__global__ void __launch_bounds__(256)
k_fin2(float* __restrict__ out, const float* __restrict__ verts)
{
    int v = blockIdx.x * blockDim.x + threadIdx.x;
    if (v >= NV) return;

    int d = g_cursor[v];
    int o = v * BCAP;
    float ax = 0.0f, ay = 0.0f, az = 0.0f;
    int k = 0;
    for (; k + 4 <= d; k += 4) {
        int s0 = g_csr[o + k],     s1 = g_csr[o + k + 1];
        int s2 = g_csr[o + k + 2], s3 = g_csr[o + k + 3];
        float4 p0 = g_P[s0], p1 = g_P[s1], p2 = g_P[s2], p3 = g_P[s3];
        ax += (p0.x + p1.x) + (p2.x + p3.x);
        ay += (p0.y + p1.y) + (p2.y + p3.y);
        az += (p0.z + p1.z) + (p2.z + p3.z);
    }
    for (; k < d; k++) {
        float4 p = g_P[g_csr[o + k]];
        ax += p.x; ay += p.y; az += p.z;
    }
    float idg = 1.0f / fmaxf((float)d, 1.0f);
    float4 S = g_S[v];
    out[v * 3 + 0] = verts[v * 3 + 0] + 0.1f * (S.x + idg * ax);
    out[v * 3 + 1] = verts[v * 3 + 1] + 0.1f * (S.y + idg * ay);
    out[v * 3 + 2] = verts[v * 3 + 2] + 0.1f * (S.z + idg * az);

    g_cursor[v] = 0;   // leave zeroed for next launch (graph replay)
}

// ---------------- launch ----------------
extern "C" void kernel_launch(void* const* d_in, const int* in_sizes, int n_in,
                              void* d_out, int out_size)
{
    const float* img   = (const float*)d_in[0];
    const float* verts = (const float*)d_in[1];
    const int*   esrc  = (const int*)d_in[2];
    const int*   edst  = (const int*)d_in[3];
    const float* ws0 = (const float*)d_in[4];
    const float* wn0 = (const float*)d_in[5];
    const float* b0  = (const float*)d_in[6];
    const float* ws1 = (const float*)d_in[7];
    const float* wn1 = (const float*)d_in[8];
    const float* b1  = (const float*)d_in[9];
    const float* ws2 = (const float*)d_in[10];
    const float* wn2 = (const float*)d_in[11];
    const float* b2  = (const float*)d_in[12];
    const float* ws3 = (const float*)d_in[13];
    const float* wn3 = (const float*)d_in[14];
    const float* b3  = (const float*)d_in[15];
    float* out = (float*)d_out;

    __nv_bfloat16 *x0p, *x1p, *x2p;
    cudaGetSymbolAddress((void**)&x0p, g_X0);
    cudaGetSymbolAddress((void**)&x1p, g_X1);
    cudaGetSymbolAddress((void**)&x2p, g_X2);

    const int TB = 256;

    k_trsc<<<TR_BLOCKS + SC_BLOCKS, 128>>>(img, (const int4*)esrc, (const int4*)edst);
    k_sample<<<(NV + TB - 1) / TB, TB>>>(verts);

    k_layer<128, 64, 32, true, false><<<(NV + 127) / 128, TB>>>(
        x0p, x1p, ws0, wn0, b0, 19, nullptr, nullptr, nullptr);
    k_layer<128, 64, 64, true, false><<<(NV + 127) / 128, TB>>>(
        x1p, x2p, ws1, wn1, b1, 32, nullptr, nullptr, nullptr);
    k_layer<64, 128, 64, true, true><<<(NV + 63) / 64, TB>>>(
        x2p, nullptr, ws2, wn2, b2, 64, ws3, wn3, b3);

    k_fin2<<<(NV + TB - 1) / TB, TB>>>(out, verts);
}

// round 13
// speedup vs baseline: 1.1380x; 1.1380x over previous
#include <cuda_runtime.h>
#include <cuda_bf16.h>

typedef unsigned long long ull;
typedef unsigned int u32;

#define NV      100000
#define NE      1600000
#define GRIDW   128
#define G3      (GRIDW*GRIDW*GRIDW)
#define BCAP    128          // neighbor bucket capacity per vertex

// ---------------- device scratch ----------------
__device__ int   g_cursor[NV];     // zero-init; k_fin2 re-zeroes each launch
__device__ int   g_csr[NV * BCAP];

__device__ __align__(16) __nv_bfloat16 g_IT[G3 * 16];      // channels-last image
__device__ __align__(16) __nv_bfloat16 g_X0[(NV + 1) * 32]; // row NV stays zero
__device__ __align__(16) __nv_bfloat16 g_X1[(NV + 1) * 32];
__device__ __align__(16) __nv_bfloat16 g_X2[(NV + 1) * 64];
__device__ __align__(16) __nv_bfloat16 g_G32[NV * 32];
__device__ __align__(16) __nv_bfloat16 g_G64[NV * 64];
__device__ float4 g_P[NV];    // h3 @ Wn3
__device__ float4 g_S[NV];    // h3 @ Ws3 + b3

// ---------------- helpers ----------------
__device__ __forceinline__ ull pack2(float lo, float hi) {
    ull r; asm("mov.b64 %0, {%1,%2};" : "=l"(r) : "f"(lo), "f"(hi)); return r;
}
__device__ __forceinline__ float2 unpack2(ull v) {
    float2 f; asm("mov.b64 {%0,%1}, %2;" : "=f"(f.x), "=f"(f.y) : "l"(v)); return f;
}
__device__ __forceinline__ ull add2(ull a, ull b) {
    ull d; asm("add.rn.f32x2 %0, %1, %2;" : "=l"(d) : "l"(a), "l"(b)); return d;
}
__device__ __forceinline__ ull mul2(ull a, ull b) {
    ull d; asm("mul.rn.f32x2 %0, %1, %2;" : "=l"(d) : "l"(a), "l"(b)); return d;
}
__device__ __forceinline__ ull bf2f2(u32 p) {
    u32 lo = p << 16;
    u32 hi = p & 0xFFFF0000u;
    ull r; asm("mov.b64 %0, {%1,%2};" : "=l"(r) : "r"(lo), "r"(hi)); return r;
}
__device__ __forceinline__ u32 f2bf2(ull v) {
    float2 f = unpack2(v);
    __nv_bfloat162 b = __float22bfloat162_rn(f);
    return *(u32*)&b;
}
__device__ __forceinline__ u32 f2bf2s(float lo, float hi) {
    __nv_bfloat162 b = __float22bfloat162_rn(make_float2(lo, hi));
    return *(u32*)&b;
}
__device__ __forceinline__ u32 smaddr(const void* p) {
    return (u32)__cvta_generic_to_shared(p);
}
__device__ __forceinline__ void ldsm_x4(u32& r0, u32& r1, u32& r2, u32& r3, u32 a) {
    asm volatile("ldmatrix.sync.aligned.m8n8.x4.shared.b16 {%0,%1,%2,%3}, [%4];"
                 : "=r"(r0), "=r"(r1), "=r"(r2), "=r"(r3) : "r"(a));
}
__device__ __forceinline__ void ldsm_x2(u32& r0, u32& r1, u32 a) {
    asm volatile("ldmatrix.sync.aligned.m8n8.x2.shared.b16 {%0,%1}, [%2];"
                 : "=r"(r0), "=r"(r1) : "r"(a));
}
__device__ __forceinline__ void mma_bf16(float& d0, float& d1, float& d2, float& d3,
                                         u32 a0, u32 a1, u32 a2, u32 a3,
                                         u32 b0, u32 b1) {
    asm volatile(
        "mma.sync.aligned.m16n8k16.row.col.f32.bf16.bf16.f32 "
        "{%0,%1,%2,%3}, {%4,%5,%6,%7}, {%8,%9}, {%0,%1,%2,%3};"
        : "+f"(d0), "+f"(d1), "+f"(d2), "+f"(d3)
        : "r"(a0), "r"(a1), "r"(a2), "r"(a3), "r"(b0), "r"(b1));
}

// ---------------- fused: image transpose || edge scatter ----------------
#define TR_BLOCKS (GRIDW * GRIDW)
#define SC_BLOCKS (NE / 4 / 128)       // 3125

__global__ void __launch_bounds__(128)
k_trsc(const float* __restrict__ img,
       const int4* __restrict__ src4, const int4* __restrict__ dst4)
{
    __shared__ __align__(16) __nv_bfloat16 s[128 * 16];
    int t = threadIdx.x;
    if (blockIdx.x < TR_BLOCKS) {
        int base = blockIdx.x * 128;
#pragma unroll
        for (int c = 0; c < 16; c++) {
            float v = img[(size_t)c * G3 + base + t];
            s[t * 16 + c] = __float2bfloat16(v);
        }
        __syncthreads();
        const uint4* sp = (const uint4*)s;
        uint4* gp = (uint4*)&g_IT[(size_t)base * 16];
        gp[t]       = sp[t];
        gp[t + 128] = sp[t + 128];
    } else {
        int e = (blockIdx.x - TR_BLOCKS) * 128 + t;
        int4 sv = src4[e];
        int4 dv = dst4[e];
        int p;
        p = atomicAdd(&g_cursor[dv.x], 1); g_csr[dv.x * BCAP + p] = sv.x;
        p = atomicAdd(&g_cursor[dv.y], 1); g_csr[dv.y * BCAP + p] = sv.y;
        p = atomicAdd(&g_cursor[dv.z], 1); g_csr[dv.z * BCAP + p] = sv.z;
        p = atomicAdd(&g_cursor[dv.w], 1); g_csr[dv.w * BCAP + p] = sv.w;
    }
}

// ---------------- trilinear sampling + bucket padding ----------------
__global__ void __launch_bounds__(256)
k_sample(const float* __restrict__ verts)
{
    int v = blockIdx.x * blockDim.x + threadIdx.x;
    if (v >= NV) return;

    // pad bucket to multiple of 8 with zero-row index NV (scatter already done)
    {
        int d = g_cursor[v];
        int dp = (d + 7) & ~7;
        if (dp > BCAP) dp = BCAP;
        for (int k = d; k < dp; k++) g_csr[v * BCAP + k] = NV;
    }

    float px = verts[v * 3 + 0];
    float py = verts[v * 3 + 1];
    float pz = verts[v * 3 + 2];

    float cx = fminf(fmaxf(px, 0.0f), 127.0f);
    float cy = fminf(fmaxf(py, 0.0f), 127.0f);
    float cz = fminf(fmaxf(pz, 0.0f), 127.0f);
    float fx0 = floorf(cx), fy0 = floorf(cy), fz0 = floorf(cz);
    int x0 = (int)fx0, y0 = (int)fy0, z0 = (int)fz0;
    int x1 = min(x0 + 1, 127), y1 = min(y0 + 1, 127), z1 = min(z0 + 1, 127);
    float wx = cx - fx0, wy = cy - fy0, wz = cz - fz0;

    float f[16];
#pragma unroll
    for (int c = 0; c < 16; c++) f[c] = 0.0f;

    int xs[2] = {x0, x1}; int ys[2] = {y0, y1}; int zs[2] = {z0, z1};
    float wxa[2] = {1.0f - wx, wx};
    float wya[2] = {1.0f - wy, wy};
    float wza[2] = {1.0f - wz, wz};

#pragma unroll
    for (int a = 0; a < 2; a++)
#pragma unroll
    for (int b = 0; b < 2; b++)
#pragma unroll
    for (int cc = 0; cc < 2; cc++) {
        float w = wxa[a] * wya[b] * wza[cc];
        size_t idx = ((size_t)((xs[a] << 14) + (ys[b] << 7) + zs[cc])) << 4;
        uint4 p0 = *(const uint4*)&g_IT[idx];
        uint4 p1 = *(const uint4*)&g_IT[idx + 8];
        const u32 pk[8] = {p0.x, p0.y, p0.z, p0.w, p1.x, p1.y, p1.z, p1.w};
#pragma unroll
        for (int j = 0; j < 8; j++) {
            float2 two = unpack2(bf2f2(pk[j]));
            f[2 * j]     += w * two.x;
            f[2 * j + 1] += w * two.y;
        }
    }

    float e[32];
    e[0] = px * (1.0f / 128.0f);
    e[1] = py * (1.0f / 128.0f);
    e[2] = pz * (1.0f / 128.0f);
#pragma unroll
    for (int c = 0; c < 16; c++) e[3 + c] = f[c];
#pragma unroll
    for (int c = 19; c < 32; c++) e[c] = 0.0f;

    u32 w8[16];
#pragma unroll
    for (int j = 0; j < 16; j++) w8[j] = f2bf2s(e[2 * j], e[2 * j + 1]);
    uint4* dst = (uint4*)&g_X0[(size_t)v * 32];
    dst[0] = make_uint4(w8[0], w8[1], w8[2], w8[3]);
    dst[1] = make_uint4(w8[4], w8[5], w8[6], w8[7]);
    dst[2] = make_uint4(w8[8], w8[9], w8[10], w8[11]);
    dst[3] = make_uint4(w8[12], w8[13], w8[14], w8[15]);
}

// ---------------- gather: mean of neighbor rows, warp per vertex ----------------
// 16 lanes per row (u32 for DIN=32, uint2 for DIN=64); 2 neighbors per step
// (sub = lane>>4); buckets padded to mult of 8 with zero-row NV -> no predicates.
template<int DIN>
__global__ void __launch_bounds__(256)
k_gather(const __nv_bfloat16* __restrict__ X, __nv_bfloat16* __restrict__ G)
{
    constexpr int EPL = DIN / 16;       // bf16 elements per lane (2 or 4)

    int warp = threadIdx.x >> 5, lane = threadIdx.x & 31;
    int sub = lane >> 4;
    int cole = (lane & 15) * EPL;

    int v = blockIdx.x * 8 + warp;
    if (v >= NV) return;

    int d = g_cursor[v];
    int dp = (d + 1) & ~1;              // padded slots valid up to round8(d) >= dp
    int o = v * BCAP;

    ull a0 = 0ull, a1 = 0ull;
    for (int kb = 0; kb < dp; kb += 32) {
        int idx = (kb + lane < dp) ? g_csr[o + kb + lane] : 0;
        int klim = min(dp - kb, 32);
#pragma unroll 4
        for (int k = 0; k < klim; k += 2) {
            int s = __shfl_sync(0xFFFFFFFFu, idx, k + sub);
            if (DIN == 32) {
                u32 p = *(const u32*)&X[(size_t)s * DIN + cole];
                a0 = add2(a0, bf2f2(p));
            } else {
                uint2 p = *(const uint2*)&X[(size_t)s * DIN + cole];
                a0 = add2(a0, bf2f2(p.x));
                a1 = add2(a1, bf2f2(p.y));
            }
        }
    }

    a0 = add2(a0, __shfl_xor_sync(0xFFFFFFFFu, a0, 16));
    if (DIN == 64) a1 = add2(a1, __shfl_xor_sync(0xFFFFFFFFu, a1, 16));

    float inv = 1.0f / fmaxf((float)d, 1.0f);
    ull inv2 = pack2(inv, inv);
    if (sub == 0) {
        if (DIN == 32) {
            *(u32*)&G[(size_t)v * DIN + cole] = f2bf2(mul2(a0, inv2));
        } else {
            uint2 ov;
            ov.x = f2bf2(mul2(a0, inv2));
            ov.y = f2bf2(mul2(a1, inv2));
            *(uint2*)&G[(size_t)v * DIN + cole] = ov;
        }
    }
}

// ---------------- tensor-core layer GEMM (separate from gather) ----------------
template<int M, int K, int DOUT, bool RELU, bool PROJ>
__global__ void __launch_bounds__(256)
k_gemm(const __nv_bfloat16* __restrict__ X, const __nv_bfloat16* __restrict__ G,
       __nv_bfloat16* __restrict__ Y,
       const float* __restrict__ Wsg, const float* __restrict__ Wng,
       const float* __restrict__ Bg, int din_real,
       const float* __restrict__ Ws3, const float* __restrict__ Wn3,
       const float* __restrict__ B3)
{
    constexpr int RS  = K + 8;
    constexpr int DIN = K / 2;
    constexpr int C8  = K / 8;
    constexpr int NT  = DOUT / 16;
    constexpr int MH  = M / 64;

    __shared__ __align__(16) __nv_bfloat16 As[M * RS];
    __shared__ __align__(16) __nv_bfloat16 Wt[DOUT * RS];
    __shared__ float Bs[DOUT];

    int tid = threadIdx.x;
    int warp = tid >> 5, lane = tid & 31;
    int vbase = blockIdx.x * M;

    for (int idx = tid; idx < DOUT * K; idx += 256) {
        int n = idx / K, k = idx % K;
        int kh = (k < DIN) ? k : k - DIN;
        float val = 0.0f;
        if (kh < din_real) val = ((k < DIN) ? Wsg : Wng)[kh * DOUT + n];
        Wt[n * RS + k] = __float2bfloat16(val);
    }
    if (tid < DOUT) Bs[tid] = Bg[tid];

    for (int idx = tid; idx < M * C8; idx += 256) {
        int r = idx / C8, c8 = idx % C8;
        int v = min(vbase + r, NV - 1);
        const __nv_bfloat16* src = (c8 < C8 / 2)
            ? &X[(size_t)v * DIN + c8 * 8]
            : &G[(size_t)v * DIN + (c8 - C8 / 2) * 8];
        *(uint4*)&As[r * RS + c8 * 8] = *(const uint4*)src;
    }
    __syncthreads();

    int wm = warp & 3;
    int wn = warp >> 2;
    int nb = wn * (DOUT / 2);

    float d[MH][NT][4];
#pragma unroll
    for (int nt = 0; nt < NT; nt++) {
        float c0 = Bs[nb + nt * 8 + (lane & 3) * 2];
        float c1 = Bs[nb + nt * 8 + (lane & 3) * 2 + 1];
#pragma unroll
        for (int mh = 0; mh < MH; mh++) {
            d[mh][nt][0] = c0; d[mh][nt][1] = c1;
            d[mh][nt][2] = c0; d[mh][nt][3] = c1;
        }
    }

#pragma unroll
    for (int ks = 0; ks < K / 16; ks++) {
        int k0 = ks * 16;
        u32 a[MH][4];
#pragma unroll
        for (int mh = 0; mh < MH; mh++) {
            int m0 = mh * 64 + wm * 16;
            u32 aaddr = smaddr(&As[(m0 + (lane & 15)) * RS + k0 + (lane >> 4) * 8]);
            ldsm_x4(a[mh][0], a[mh][1], a[mh][2], a[mh][3], aaddr);
        }
#pragma unroll
        for (int nt = 0; nt < NT; nt++) {
            u32 b0, b1;
            u32 baddr = smaddr(&Wt[(nb + nt * 8 + (lane & 7)) * RS + k0 + ((lane >> 3) & 1) * 8]);
            ldsm_x2(b0, b1, baddr);
#pragma unroll
            for (int mh = 0; mh < MH; mh++)
                mma_bf16(d[mh][nt][0], d[mh][nt][1], d[mh][nt][2], d[mh][nt][3],
                         a[mh][0], a[mh][1], a[mh][2], a[mh][3], b0, b1);
        }
    }

    if (PROJ) __syncthreads();

#pragma unroll
    for (int mh = 0; mh < MH; mh++) {
        int rb = mh * 64 + wm * 16 + (lane >> 2);
#pragma unroll
        for (int nt = 0; nt < NT; nt++) {
            int col = nb + nt * 8 + (lane & 3) * 2;
            float y0 = d[mh][nt][0], y1 = d[mh][nt][1], y2 = d[mh][nt][2], y3 = d[mh][nt][3];
            if (RELU) {
                y0 = fmaxf(y0, 0.3f * y0); y1 = fmaxf(y1, 0.3f * y1);
                y2 = fmaxf(y2, 0.3f * y2); y3 = fmaxf(y3, 0.3f * y3);
            }
            if (PROJ) {
                float* r0 = (float*)&As[(size_t)rb * RS];
                float* r1 = (float*)&As[(size_t)(rb + 8) * RS];
                r0[col] = y0; r0[col + 1] = y1;
                r1[col] = y2; r1[col + 1] = y3;
            } else {
                int row0 = vbase + rb;
                if (row0 < NV)
                    *(u32*)&Y[(size_t)row0 * DOUT + col] = f2bf2s(y0, y1);
                if (row0 + 8 < NV)
                    *(u32*)&Y[(size_t)(row0 + 8) * DOUT + col] = f2bf2s(y2, y3);
            }
        }
    }

    if (PROJ) {
        __syncthreads();
        float ws[2][3], wnv[2][3];
#pragma unroll
        for (int e2 = 0; e2 < 2; e2++)
#pragma unroll
            for (int c = 0; c < 3; c++) {
                ws[e2][c]  = Ws3[(2 * lane + e2) * 3 + c];
                wnv[e2][c] = Wn3[(2 * lane + e2) * 3 + c];
            }
        float b0 = B3[0], b1 = B3[1], b2 = B3[2];

        for (int i = 0; i < M / 8; i++) {
            int r = warp * (M / 8) + i;
            int v = vbase + r;
            if (v >= NV) break;
            const float* hrow = (const float*)&As[(size_t)r * RS];
            float2 h2 = *(const float2*)&hrow[2 * lane];
            float as[3], an[3];
#pragma unroll
            for (int c = 0; c < 3; c++) {
                as[c] = h2.x * ws[0][c] + h2.y * ws[1][c];
                an[c] = h2.x * wnv[0][c] + h2.y * wnv[1][c];
            }
#pragma unroll
            for (int off = 16; off > 0; off >>= 1) {
#pragma unroll
                for (int c = 0; c < 3; c++) {
                    as[c] += __shfl_xor_sync(0xFFFFFFFFu, as[c], off);
                    an[c] += __shfl_xor_sync(0xFFFFFFFFu, an[c], off);
                }
            }
            if (lane == 0) {
                g_S[v] = make_float4(as[0] + b0, as[1] + b1, as[2] + b2, 0.0f);
                g_P[v] = make_float4(an[0], an[1], an[2], 0.0f);
            }
        }
    }
}

// ---------------- final: 3-wide gather + output (+ cursor re-zero) ----------------
__global__ void __launch_bounds__(256)
k_fin2(float* __restrict__ out, const float* __restrict__ verts)
{
    int v = blockIdx.x * blockDim.x + threadIdx.x;
    if (v >= NV) return;

    int d = g_cursor[v];
    int o = v * BCAP;
    float ax = 0.0f, ay = 0.0f, az = 0.0f;
    int k = 0;
    for (; k + 4 <= d; k += 4) {
        int s0 = g_csr[o + k],     s1 = g_csr[o + k + 1];
        int s2 = g_csr[o + k + 2], s3 = g_csr[o + k + 3];
        float4 p0 = g_P[s0], p1 = g_P[s1], p2 = g_P[s2], p3 = g_P[s3];
        ax += (p0.x + p1.x) + (p2.x + p3.x);
        ay += (p0.y + p1.y) + (p2.y + p3.y);
        az += (p0.z + p1.z) + (p2.z + p3.z);
    }
    for (; k < d; k++) {
        float4 p = g_P[g_csr[o + k]];
        ax += p.x; ay += p.y; az += p.z;
    }
    float idg = 1.0f / fmaxf((float)d, 1.0f);
    float4 S = g_S[v];
    out[v * 3 + 0] = verts[v * 3 + 0] + 0.1f * (S.x + idg * ax);
    out[v * 3 + 1] = verts[v * 3 + 1] + 0.1f * (S.y + idg * ay);
    out[v * 3 + 2] = verts[v * 3 + 2] + 0.1f * (S.z + idg * az);

    g_cursor[v] = 0;   // leave zeroed for next launch (graph replay)
}

// ---------------- launch ----------------
extern "C" void kernel_launch(void* const* d_in, const int* in_sizes, int n_in,
                              void* d_out, int out_size)
{
    const float* img   = (const float*)d_in[0];
    const float* verts = (const float*)d_in[1];
    const int*   esrc  = (const int*)d_in[2];
    const int*   edst  = (const int*)d_in[3];
    const float* ws0 = (const float*)d_in[4];
    const float* wn0 = (const float*)d_in[5];
    const float* b0  = (const float*)d_in[6];
    const float* ws1 = (const float*)d_in[7];
    const float* wn1 = (const float*)d_in[8];
    const float* b1  = (const float*)d_in[9];
    const float* ws2 = (const float*)d_in[10];
    const float* wn2 = (const float*)d_in[11];
    const float* b2  = (const float*)d_in[12];
    const float* ws3 = (const float*)d_in[13];
    const float* wn3 = (const float*)d_in[14];
    const float* b3  = (const float*)d_in[15];
    float* out = (float*)d_out;

    __nv_bfloat16 *x0p, *x1p, *x2p, *g32p, *g64p;
    cudaGetSymbolAddress((void**)&x0p, g_X0);
    cudaGetSymbolAddress((void**)&x1p, g_X1);
    cudaGetSymbolAddress((void**)&x2p, g_X2);
    cudaGetSymbolAddress((void**)&g32p, g_G32);
    cudaGetSymbolAddress((void**)&g64p, g_G64);

    const int TB = 256;
    const int GW = (NV + 7) / 8;

    k_trsc<<<TR_BLOCKS + SC_BLOCKS, 128>>>(img, (const int4*)esrc, (const int4*)edst);
    k_sample<<<(NV + TB - 1) / TB, TB>>>(verts);

    k_gather<32><<<GW, TB>>>(x0p, g32p);
    k_gemm<256, 64, 32, true, false><<<(NV + 255) / 256, TB>>>(
        x0p, g32p, x1p, ws0, wn0, b0, 19, nullptr, nullptr, nullptr);

    k_gather<32><<<GW, TB>>>(x1p, g32p);
    k_gemm<256, 64, 64, true, false><<<(NV + 255) / 256, TB>>>(
        x1p, g32p, x2p, ws1, wn1, b1, 32, nullptr, nullptr, nullptr);

    k_gather<64><<<GW, TB>>>(x2p, g64p);
    k_gemm<128, 128, 64, true, true><<<(NV + 127) / 128, TB>>>(
        x2p, g64p, nullptr, ws2, wn2, b2, 64, ws3, wn3, b3);

    k_fin2<<<(NV + TB - 1) / TB, TB>>>(out, verts);
}